// round 7
// baseline (speedup 1.0000x reference)
#include <cuda_runtime.h>
#include <math.h>

#define Nn 50000
#define En 800000
#define Cc 16
#define Mm 32
#define Gg 8
#define CG (Cc*Gg)          // 128

// ---- scratch (module-static, allowed) ----
// NOTE: g_post0 / g_aggr use INTERNAL layout [N][G][C]  (c innermost!)
__device__ float g_smB0[Cc*Mm*Gg];   // softmax(B0, axis=M)
__device__ float g_smPi[Cc*Gg];      // softmax(Pi, axis=C)
__device__ float g_smB1[Cc*Mm*Gg];   // softmax(B1, axis=M)
__device__ float g_smQ[Cc*Cc*Gg];    // softmax(Q, axis=0 (i))
__device__ float g_post0[(size_t)Nn*CG];
__device__ float g_aggr[(size_t)Nn*CG];
__device__ float g_cnt[Nn];

// ---------------------------------------------------------------------------
// 1) All four softmaxes in one small block (128 threads).
// ---------------------------------------------------------------------------
__global__ void k_softmax(const float* __restrict__ B0, const float* __restrict__ Pi,
                          const float* __restrict__ B1, const float* __restrict__ Q)
{
    int t = threadIdx.x;
    if (t >= 128) return;
    int g = t & 7;
    int r = t >> 3;

    // B0 row (c=r, g): softmax over m
    {
        float mx = -1e30f;
        #pragma unroll
        for (int m = 0; m < Mm; m++) mx = fmaxf(mx, B0[r*Mm*Gg + m*Gg + g]);
        float e[Mm]; float s = 0.f;
        #pragma unroll
        for (int m = 0; m < Mm; m++) { e[m] = expf(B0[r*Mm*Gg + m*Gg + g] - mx); s += e[m]; }
        float inv = 1.f / s;
        #pragma unroll
        for (int m = 0; m < Mm; m++) g_smB0[r*Mm*Gg + m*Gg + g] = e[m] * inv;
    }
    // B1 row (c=r, g)
    {
        float mx = -1e30f;
        #pragma unroll
        for (int m = 0; m < Mm; m++) mx = fmaxf(mx, B1[r*Mm*Gg + m*Gg + g]);
        float e[Mm]; float s = 0.f;
        #pragma unroll
        for (int m = 0; m < Mm; m++) { e[m] = expf(B1[r*Mm*Gg + m*Gg + g] - mx); s += e[m]; }
        float inv = 1.f / s;
        #pragma unroll
        for (int m = 0; m < Mm; m++) g_smB1[r*Mm*Gg + m*Gg + g] = e[m] * inv;
    }
    // Q column (l=r, g): softmax over i (dim 0)
    {
        float mx = -1e30f;
        #pragma unroll
        for (int i = 0; i < Cc; i++) mx = fmaxf(mx, Q[i*Cc*Gg + r*Gg + g]);
        float e[Cc]; float s = 0.f;
        #pragma unroll
        for (int i = 0; i < Cc; i++) { e[i] = expf(Q[i*Cc*Gg + r*Gg + g] - mx); s += e[i]; }
        float inv = 1.f / s;
        #pragma unroll
        for (int i = 0; i < Cc; i++) g_smQ[i*Cc*Gg + r*Gg + g] = e[i] * inv;
    }
    // Pi column g (threads 0..7): softmax over c
    if (t < Gg) {
        float mx = -1e30f;
        #pragma unroll
        for (int c = 0; c < Cc; c++) mx = fmaxf(mx, Pi[c*Gg + t]);
        float e[Cc]; float s = 0.f;
        #pragma unroll
        for (int c = 0; c < Cc; c++) { e[c] = expf(Pi[c*Gg + t] - mx); s += e[c]; }
        float inv = 1.f / s;
        #pragma unroll
        for (int c = 0; c < Cc; c++) g_smPi[c*Gg + t] = e[c] * inv;
    }
}

// ---------------------------------------------------------------------------
// 2) Layer 0 + zeroing fused. Thread (n,g) writes post0[n][g][0..15] as
//    4x STG.128 (and zeroes aggr the same way) -> fully coalesced.
// ---------------------------------------------------------------------------
__global__ void k_layer0(const int* __restrict__ x, float* __restrict__ out)
{
    int idx = blockIdx.x * blockDim.x + threadIdx.x;
    if (idx >= Nn * Gg) return;
    int n = idx >> 3, g = idx & 7;
    int xm = x[n];
    float u[Cc]; float s = 0.f;
    #pragma unroll
    for (int c = 0; c < Cc; c++) {
        u[c] = g_smPi[c*Gg + g] * g_smB0[c*Mm*Gg + xm*Gg + g];
        s += u[c];
    }
    out[(size_t)n * (2*Gg) + g] = logf(s);   // ll layer 0
    float inv = 1.f / s;

    float4* p = reinterpret_cast<float4*>(g_post0 + (size_t)n * CG + g * Cc);
    float4* z = reinterpret_cast<float4*>(g_aggr  + (size_t)n * CG + g * Cc);
    const float4 z4 = make_float4(0.f, 0.f, 0.f, 0.f);
    #pragma unroll
    for (int q = 0; q < 4; q++) {
        p[q] = make_float4(u[q*4+0]*inv, u[q*4+1]*inv, u[q*4+2]*inv, u[q*4+3]*inv);
        z[q] = z4;
    }
    if (g == 0) g_cnt[n] = 0.f;
}

// ---------------------------------------------------------------------------
// 3) Scatter-add, one WARP per FOUR edges (unchanged; layout-agnostic:
//    copies whole 128-float rows). MLP=4 LDG.128 then 4 RED.128.
// ---------------------------------------------------------------------------
__global__ void k_scatter(const int* __restrict__ ei)
{
    int wid  = (blockIdx.x * blockDim.x + threadIdx.x) >> 5;  // warp id
    int lane = threadIdx.x & 31;
    int e0   = wid * 4;                                       // grid sized exactly

    const int4 S = *reinterpret_cast<const int4*>(ei + e0);        // 4 src
    const int4 D = *reinterpret_cast<const int4*>(ei + En + e0);   // 4 dst

    if (lane == 0) {
        atomicAdd(&g_cnt[S.x], 1.0f);
        atomicAdd(&g_cnt[S.y], 1.0f);
        atomicAdd(&g_cnt[S.z], 1.0f);
        atomicAdd(&g_cnt[S.w], 1.0f);
    }

    const int off = lane * 4;
    const float4 v0 = *reinterpret_cast<const float4*>(g_post0 + (size_t)D.x * CG + off);
    const float4 v1 = *reinterpret_cast<const float4*>(g_post0 + (size_t)D.y * CG + off);
    const float4 v2 = *reinterpret_cast<const float4*>(g_post0 + (size_t)D.z * CG + off);
    const float4 v3 = *reinterpret_cast<const float4*>(g_post0 + (size_t)D.w * CG + off);

    float* p0 = g_aggr + (size_t)S.x * CG + off;
    float* p1 = g_aggr + (size_t)S.y * CG + off;
    float* p2 = g_aggr + (size_t)S.z * CG + off;
    float* p3 = g_aggr + (size_t)S.w * CG + off;

    asm volatile("red.global.add.v4.f32 [%0], {%1, %2, %3, %4};"
                 :: "l"(p0), "f"(v0.x), "f"(v0.y), "f"(v0.z), "f"(v0.w) : "memory");
    asm volatile("red.global.add.v4.f32 [%0], {%1, %2, %3, %4};"
                 :: "l"(p1), "f"(v1.x), "f"(v1.y), "f"(v1.z), "f"(v1.w) : "memory");
    asm volatile("red.global.add.v4.f32 [%0], {%1, %2, %3, %4};"
                 :: "l"(p2), "f"(v2.x), "f"(v2.y), "f"(v2.z), "f"(v2.w) : "memory");
    asm volatile("red.global.add.v4.f32 [%0], {%1, %2, %3, %4};"
                 :: "l"(p3), "f"(v3.x), "f"(v3.y), "f"(v3.z), "f"(v3.w) : "memory");
}

// ---------------------------------------------------------------------------
// 4) Layer 1. Thread (n,g): 4x LDG.128 of aggr[n][g][:] (coalesced), dot
//    products against Q, then stage post1 row in padded smem and do a
//    block-cooperative coalesced STG.128 copy to the output layout [N][C][G].
// ---------------------------------------------------------------------------
__global__ void k_layer1(const int* __restrict__ x, float* __restrict__ out)
{
    __shared__ float s_out[32 * 132];            // 32 nodes/block, rows padded

    int idx = blockIdx.x * blockDim.x + threadIdx.x;
    int n = idx >> 3, g = idx & 7;
    int nl = threadIdx.x >> 3;                   // local node 0..31
    bool active = (idx < Nn * Gg);

    if (active) {
        int xm = x[n];
        float inv_cnt = 1.f / fmaxf(g_cnt[n], 1.f);

        const float4* ap = reinterpret_cast<const float4*>(g_aggr + (size_t)n * CG + g * Cc);
        float4 A0 = ap[0], A1 = ap[1], A2 = ap[2], A3 = ap[3];
        float a[Cc] = {A0.x,A0.y,A0.z,A0.w, A1.x,A1.y,A1.z,A1.w,
                       A2.x,A2.y,A2.z,A2.w, A3.x,A3.y,A3.z,A3.w};
        #pragma unroll
        for (int l = 0; l < Cc; l++) a[l] *= inv_cnt;

        float tv[Cc]; float norm = 0.f;
        #pragma unroll
        for (int i = 0; i < Cc; i++) {
            float s = 0.f;
            #pragma unroll
            for (int l = 0; l < Cc; l++) s += g_smQ[i*Cc*Gg + l*Gg + g] * a[l];
            float v = g_smB1[i*Mm*Gg + xm*Gg + g] * s;
            tv[i] = v;
            norm += v;
        }
        out[(size_t)n * (2*Gg) + Gg + g] = logf(norm);   // ll layer 1
        float invn = 1.f / norm;
        #pragma unroll
        for (int i = 0; i < Cc; i++) s_out[nl*132 + i*Gg + g] = tv[i] * invn;
    }
    __syncthreads();

    // cooperative coalesced copy: 256 threads x 16 floats = 32 rows x 128
    int t  = threadIdx.x;
    int cn = t >> 3;                 // local node for copy
    int co = (t & 7) * 16;           // float offset within the 128-float row
    int gn = blockIdx.x * 32 + cn;   // global node
    if (gn < Nn) {
        float* p1 = out + (size_t)Nn * 2 * Gg;
        const float4* sp = reinterpret_cast<const float4*>(s_out + cn*132 + co);
        float4* dp = reinterpret_cast<float4*>(p1 + (size_t)gn * CG + co);
        dp[0] = sp[0]; dp[1] = sp[1]; dp[2] = sp[2]; dp[3] = sp[3];
    }
}

// ---------------------------------------------------------------------------
extern "C" void kernel_launch(void* const* d_in, const int* in_sizes, int n_in,
                              void* d_out, int out_size)
{
    const int*   x  = (const int*)  d_in[0];
    const int*   ei = (const int*)  d_in[1];   // [2, E]
    const float* B0 = (const float*)d_in[2];
    const float* Pi = (const float*)d_in[3];
    const float* B1 = (const float*)d_in[4];
    const float* Q  = (const float*)d_in[5];
    float* out = (float*)d_out;

    k_softmax<<<1, 128>>>(B0, Pi, B1, Q);
    k_layer0<<<(Nn * Gg + 255) / 256, 256>>>(x, out);   // also zeroes aggr/cnt
    k_scatter<<<(En / 4 * 32) / 256, 256>>>(ei);        // 25000 blocks, exact
    k_layer1<<<(Nn * Gg + 255) / 256, 256>>>(x, out);
}

// round 8
// speedup vs baseline: 2.1970x; 2.1970x over previous
#include <cuda_runtime.h>
#include <math.h>

#define Nn 50000
#define En 800000
#define Cc 16
#define Mm 32
#define Gg 8
#define CG (Cc*Gg)          // 128

// ---- scratch (module-static, allowed) ----
__device__ float g_smB0[Cc*Mm*Gg];   // softmax(B0, axis=M)   [c][m][g]
__device__ float g_smPi[Cc*Gg];      // softmax(Pi, axis=C)   [c][g]
__device__ float g_smB1[Cc*Mm*Gg];   // softmax(B1, axis=M)   [c][m][g]
__device__ float g_smQ[Cc*Cc*Gg];    // softmax(Q, axis=0)    [i][l][g]
__device__ float g_R[Gg*Mm*Cc];      // R[g][m][i] = sum_l Q[i,l,g]*post0_tab[m][l,g]
__device__ float g_ll0[Mm*Gg];       // ll0_tab[m][g] = log(norm0(m,g))
__device__ int   g_hist[(size_t)Nn*Mm];  // per-node neighbor symbol histogram

// ---------------------------------------------------------------------------
// 1) Softmaxes (threads 0..127) THEN the R / ll0 tables (all 256 threads).
// ---------------------------------------------------------------------------
__global__ void k_softmax(const float* __restrict__ B0, const float* __restrict__ Pi,
                          const float* __restrict__ B1, const float* __restrict__ Q)
{
    int t = threadIdx.x;

    if (t < 128) {
        int g = t & 7;
        int r = t >> 3;

        // B0 row (c=r, g): softmax over m
        {
            float mx = -1e30f;
            #pragma unroll
            for (int m = 0; m < Mm; m++) mx = fmaxf(mx, B0[r*Mm*Gg + m*Gg + g]);
            float e[Mm]; float s = 0.f;
            #pragma unroll
            for (int m = 0; m < Mm; m++) { e[m] = expf(B0[r*Mm*Gg + m*Gg + g] - mx); s += e[m]; }
            float inv = 1.f / s;
            #pragma unroll
            for (int m = 0; m < Mm; m++) g_smB0[r*Mm*Gg + m*Gg + g] = e[m] * inv;
        }
        // B1 row (c=r, g)
        {
            float mx = -1e30f;
            #pragma unroll
            for (int m = 0; m < Mm; m++) mx = fmaxf(mx, B1[r*Mm*Gg + m*Gg + g]);
            float e[Mm]; float s = 0.f;
            #pragma unroll
            for (int m = 0; m < Mm; m++) { e[m] = expf(B1[r*Mm*Gg + m*Gg + g] - mx); s += e[m]; }
            float inv = 1.f / s;
            #pragma unroll
            for (int m = 0; m < Mm; m++) g_smB1[r*Mm*Gg + m*Gg + g] = e[m] * inv;
        }
        // Q column (l=r, g): softmax over i (dim 0)
        {
            float mx = -1e30f;
            #pragma unroll
            for (int i = 0; i < Cc; i++) mx = fmaxf(mx, Q[i*Cc*Gg + r*Gg + g]);
            float e[Cc]; float s = 0.f;
            #pragma unroll
            for (int i = 0; i < Cc; i++) { e[i] = expf(Q[i*Cc*Gg + r*Gg + g] - mx); s += e[i]; }
            float inv = 1.f / s;
            #pragma unroll
            for (int i = 0; i < Cc; i++) g_smQ[i*Cc*Gg + r*Gg + g] = e[i] * inv;
        }
        // Pi column g (threads 0..7): softmax over c
        if (t < Gg) {
            float mx = -1e30f;
            #pragma unroll
            for (int c = 0; c < Cc; c++) mx = fmaxf(mx, Pi[c*Gg + t]);
            float e[Cc]; float s = 0.f;
            #pragma unroll
            for (int c = 0; c < Cc; c++) { e[c] = expf(Pi[c*Gg + t] - mx); s += e[c]; }
            float inv = 1.f / s;
            #pragma unroll
            for (int c = 0; c < Cc; c++) g_smPi[c*Gg + t] = e[c] * inv;
        }
    }
    __syncthreads();

    // Table build: thread t -> (m = t>>3, g = t&7). 256 threads = 32m x 8g.
    {
        int m = t >> 3, g = t & 7;
        float u[Cc]; float s = 0.f;
        #pragma unroll
        for (int l = 0; l < Cc; l++) {
            u[l] = g_smPi[l*Gg + g] * g_smB0[l*Mm*Gg + m*Gg + g];
            s += u[l];
        }
        g_ll0[m*Gg + g] = logf(s);
        float inv = 1.f / s;
        #pragma unroll
        for (int i = 0; i < Cc; i++) {
            float acc = 0.f;
            #pragma unroll
            for (int l = 0; l < Cc; l++)
                acc += g_smQ[i*Cc*Gg + l*Gg + g] * u[l];
            g_R[g*Mm*Cc + m*Cc + i] = acc * inv;
        }
    }
}

// ---------------------------------------------------------------------------
// 2) Zero the histogram (int4, guarded).
// ---------------------------------------------------------------------------
__global__ void k_zero_hist()
{
    int i = blockIdx.x * blockDim.x + threadIdx.x;      // < Nn*32/4 = 400000
    if (i < Nn * Mm / 4)
        reinterpret_cast<int4*>(g_hist)[i] = make_int4(0, 0, 0, 0);
}

// ---------------------------------------------------------------------------
// 3) Histogram scatter: 4 edges per thread.
//    hist[src][x[dst]] += 1  (one 4-byte RED per edge)
// ---------------------------------------------------------------------------
__global__ void k_scatter(const int* __restrict__ ei, const int* __restrict__ x)
{
    int tid = blockIdx.x * blockDim.x + threadIdx.x;
    if (tid >= En / 4) return;
    int e0 = tid * 4;

    const int4 S = *reinterpret_cast<const int4*>(ei + e0);        // 4 src
    const int4 D = *reinterpret_cast<const int4*>(ei + En + e0);   // 4 dst

    int x0 = __ldg(x + D.x);
    int x1 = __ldg(x + D.y);
    int x2 = __ldg(x + D.z);
    int x3 = __ldg(x + D.w);

    atomicAdd(&g_hist[(size_t)S.x * Mm + x0], 1);
    atomicAdd(&g_hist[(size_t)S.y * Mm + x1], 1);
    atomicAdd(&g_hist[(size_t)S.z * Mm + x2], 1);
    atomicAdd(&g_hist[(size_t)S.w * Mm + x3], 1);
}

// ---------------------------------------------------------------------------
// 4) Layer 1 (+ ll0 lookup). Block = 32 nodes x 8 g = 256 threads.
//    tv[i] = sum_m hist[n][m] * R[g][m][i];  cnt = sum_m hist[n][m]
//    v[i]  = B1[i,x[n],g] * tv[i] / max(cnt,1);  norm = sum_i v
//    ll1 = log(norm); post1[i] = v[i]/norm
//    R staged in smem padded to 516 floats/g-row (conflict-free: 516 % 32 = 4),
//    hist rows padded to 33 ints (conflict-free broadcast).
// ---------------------------------------------------------------------------
__global__ void k_layer1(const int* __restrict__ x, float* __restrict__ out)
{
    __shared__ float s_R[Gg * 516];      // 16.5 KB
    __shared__ int   s_hist[32 * 33];    // 4.2 KB
    __shared__ int   s_x[32];

    int t   = threadIdx.x;
    int bn0 = blockIdx.x * 32;

    // cooperative load of R: thread t -> 16 consecutive floats of g-row (t>>5)
    {
        int g   = t >> 5;
        int rem = (t & 31) * 16;
        const float4* src = reinterpret_cast<const float4*>(g_R + g * (Mm*Cc) + rem);
        float4*       dst = reinterpret_cast<float4*>(s_R + g * 516 + rem);
        dst[0] = src[0]; dst[1] = src[1]; dst[2] = src[2]; dst[3] = src[3];
    }
    // cooperative load of hist: thread t -> 4 ints of node-row (t>>3)
    {
        int nl  = t >> 3;
        int col = (t & 7) * 4;
        if (bn0 + nl < Nn) {
            int4 h4 = *reinterpret_cast<const int4*>(g_hist + (size_t)(bn0 + nl) * Mm + col);
            int* hp = s_hist + nl * 33 + col;
            hp[0] = h4.x; hp[1] = h4.y; hp[2] = h4.z; hp[3] = h4.w;
        }
    }
    if (t < 32 && bn0 + t < Nn) s_x[t] = x[bn0 + t];
    __syncthreads();

    int nl = t >> 3, g = t & 7;
    int n  = bn0 + nl;
    if (n >= Nn) return;
    int xm = s_x[nl];

    float tv[Cc];
    #pragma unroll
    for (int i = 0; i < Cc; i++) tv[i] = 0.f;
    float cnt = 0.f;

    const float* Rg = s_R + g * 516;
    const int*   hp = s_hist + nl * 33;

    #pragma unroll
    for (int m = 0; m < Mm; m++) {
        float h = (float)hp[m];
        cnt += h;
        const float4* r4 = reinterpret_cast<const float4*>(Rg + m * Cc);
        float4 r0 = r4[0], r1 = r4[1], r2 = r4[2], r3 = r4[3];
        tv[ 0] += h * r0.x; tv[ 1] += h * r0.y; tv[ 2] += h * r0.z; tv[ 3] += h * r0.w;
        tv[ 4] += h * r1.x; tv[ 5] += h * r1.y; tv[ 6] += h * r1.z; tv[ 7] += h * r1.w;
        tv[ 8] += h * r2.x; tv[ 9] += h * r2.y; tv[10] += h * r2.z; tv[11] += h * r2.w;
        tv[12] += h * r3.x; tv[13] += h * r3.y; tv[14] += h * r3.z; tv[15] += h * r3.w;
    }

    float inv_cnt = 1.f / fmaxf(cnt, 1.f);
    float norm = 0.f;
    #pragma unroll
    for (int i = 0; i < Cc; i++) {
        float v = g_smB1[i*Mm*Gg + xm*Gg + g] * tv[i] * inv_cnt;
        tv[i] = v;
        norm += v;
    }

    out[(size_t)n * (2*Gg) + g]      = g_ll0[xm*Gg + g];   // ll layer 0
    out[(size_t)n * (2*Gg) + Gg + g] = logf(norm);         // ll layer 1

    float invn = 1.f / norm;
    float* p1 = out + (size_t)Nn * 2 * Gg;
    size_t pbase = (size_t)n * CG + g;
    #pragma unroll
    for (int i = 0; i < Cc; i++) p1[pbase + i*Gg] = tv[i] * invn;
}

// ---------------------------------------------------------------------------
extern "C" void kernel_launch(void* const* d_in, const int* in_sizes, int n_in,
                              void* d_out, int out_size)
{
    const int*   x  = (const int*)  d_in[0];
    const int*   ei = (const int*)  d_in[1];   // [2, E]
    const float* B0 = (const float*)d_in[2];
    const float* Pi = (const float*)d_in[3];
    const float* B1 = (const float*)d_in[4];
    const float* Q  = (const float*)d_in[5];
    float* out = (float*)d_out;

    k_softmax<<<1, 256>>>(B0, Pi, B1, Q);
    k_zero_hist<<<(Nn * Mm / 4 + 255) / 256, 256>>>();
    k_scatter<<<(En / 4 + 255) / 256, 256>>>(ei, x);
    k_layer1<<<(Nn + 31) / 32, 256>>>(x, out);
}

// round 9
// speedup vs baseline: 2.2068x; 1.0044x over previous
#include <cuda_runtime.h>
#include <math.h>

#define Nn 50000
#define En 800000
#define Cc 16
#define Mm 32
#define Gg 8
#define CG (Cc*Gg)          // 128

// ---- scratch (module-static, allowed) ----
__device__ float g_smB0[Cc*Mm*Gg];   // softmax(B0, axis=M)   [c][m][g]
__device__ float g_smPi[Cc*Gg];      // softmax(Pi, axis=C)   [c][g]
__device__ float g_smB1[Cc*Mm*Gg];   // softmax(B1, axis=M)   [c][m][g]
__device__ float g_smQ[Cc*Cc*Gg];    // softmax(Q, axis=0)    [i][l][g]
__device__ float g_R[Gg*Mm*Cc];      // R[g][m][i] = sum_l Q[i,l,g]*post0_tab[m][l,g]
__device__ float g_ll0[Mm*Gg];       // ll0_tab[m][g] = log(norm0(m,g))
__device__ int   g_hist[(size_t)Nn*Mm];  // per-node neighbor symbol histogram

// ---------------------------------------------------------------------------
// 1) Softmaxes (threads 0..127) THEN the R / ll0 tables (all 256 threads).
// ---------------------------------------------------------------------------
__global__ void k_softmax(const float* __restrict__ B0, const float* __restrict__ Pi,
                          const float* __restrict__ B1, const float* __restrict__ Q)
{
    int t = threadIdx.x;

    if (t < 128) {
        int g = t & 7;
        int r = t >> 3;

        // B0 row (c=r, g): softmax over m
        {
            float mx = -1e30f;
            #pragma unroll
            for (int m = 0; m < Mm; m++) mx = fmaxf(mx, B0[r*Mm*Gg + m*Gg + g]);
            float e[Mm]; float s = 0.f;
            #pragma unroll
            for (int m = 0; m < Mm; m++) { e[m] = expf(B0[r*Mm*Gg + m*Gg + g] - mx); s += e[m]; }
            float inv = 1.f / s;
            #pragma unroll
            for (int m = 0; m < Mm; m++) g_smB0[r*Mm*Gg + m*Gg + g] = e[m] * inv;
        }
        // B1 row (c=r, g)
        {
            float mx = -1e30f;
            #pragma unroll
            for (int m = 0; m < Mm; m++) mx = fmaxf(mx, B1[r*Mm*Gg + m*Gg + g]);
            float e[Mm]; float s = 0.f;
            #pragma unroll
            for (int m = 0; m < Mm; m++) { e[m] = expf(B1[r*Mm*Gg + m*Gg + g] - mx); s += e[m]; }
            float inv = 1.f / s;
            #pragma unroll
            for (int m = 0; m < Mm; m++) g_smB1[r*Mm*Gg + m*Gg + g] = e[m] * inv;
        }
        // Q column (l=r, g): softmax over i (dim 0)
        {
            float mx = -1e30f;
            #pragma unroll
            for (int i = 0; i < Cc; i++) mx = fmaxf(mx, Q[i*Cc*Gg + r*Gg + g]);
            float e[Cc]; float s = 0.f;
            #pragma unroll
            for (int i = 0; i < Cc; i++) { e[i] = expf(Q[i*Cc*Gg + r*Gg + g] - mx); s += e[i]; }
            float inv = 1.f / s;
            #pragma unroll
            for (int i = 0; i < Cc; i++) g_smQ[i*Cc*Gg + r*Gg + g] = e[i] * inv;
        }
        // Pi column g (threads 0..7): softmax over c
        if (t < Gg) {
            float mx = -1e30f;
            #pragma unroll
            for (int c = 0; c < Cc; c++) mx = fmaxf(mx, Pi[c*Gg + t]);
            float e[Cc]; float s = 0.f;
            #pragma unroll
            for (int c = 0; c < Cc; c++) { e[c] = expf(Pi[c*Gg + t] - mx); s += e[c]; }
            float inv = 1.f / s;
            #pragma unroll
            for (int c = 0; c < Cc; c++) g_smPi[c*Gg + t] = e[c] * inv;
        }
    }
    __syncthreads();

    // Table build: thread t -> (m = t>>3, g = t&7). 256 threads = 32m x 8g.
    {
        int m = t >> 3, g = t & 7;
        float u[Cc]; float s = 0.f;
        #pragma unroll
        for (int l = 0; l < Cc; l++) {
            u[l] = g_smPi[l*Gg + g] * g_smB0[l*Mm*Gg + m*Gg + g];
            s += u[l];
        }
        g_ll0[m*Gg + g] = logf(s);
        float inv = 1.f / s;
        #pragma unroll
        for (int i = 0; i < Cc; i++) {
            float acc = 0.f;
            #pragma unroll
            for (int l = 0; l < Cc; l++)
                acc += g_smQ[i*Cc*Gg + l*Gg + g] * u[l];
            g_R[g*Mm*Cc + m*Cc + i] = acc * inv;
        }
    }
}

// ---------------------------------------------------------------------------
// 2) Zero the histogram (int4, guarded).
// ---------------------------------------------------------------------------
__global__ void k_zero_hist()
{
    int i = blockIdx.x * blockDim.x + threadIdx.x;      // < Nn*32/4 = 400000
    if (i < Nn * Mm / 4)
        reinterpret_cast<int4*>(g_hist)[i] = make_int4(0, 0, 0, 0);
}

// ---------------------------------------------------------------------------
// 3) Histogram scatter: 4 edges per thread.
//    hist[src][x[dst]] += 1  (one 4-byte RED per edge)
// ---------------------------------------------------------------------------
__global__ void k_scatter(const int* __restrict__ ei, const int* __restrict__ x)
{
    int tid = blockIdx.x * blockDim.x + threadIdx.x;
    if (tid >= En / 4) return;
    int e0 = tid * 4;

    const int4 S = *reinterpret_cast<const int4*>(ei + e0);        // 4 src
    const int4 D = *reinterpret_cast<const int4*>(ei + En + e0);   // 4 dst

    int x0 = __ldg(x + D.x);
    int x1 = __ldg(x + D.y);
    int x2 = __ldg(x + D.z);
    int x3 = __ldg(x + D.w);

    atomicAdd(&g_hist[(size_t)S.x * Mm + x0], 1);
    atomicAdd(&g_hist[(size_t)S.y * Mm + x1], 1);
    atomicAdd(&g_hist[(size_t)S.z * Mm + x2], 1);
    atomicAdd(&g_hist[(size_t)S.w * Mm + x3], 1);
}

// ---------------------------------------------------------------------------
// 4) Layer 1 (+ ll0 lookup). Block = 32 nodes x 8 g = 256 threads.
//    tv[i] = sum_m hist[n][m] * R[g][m][i];  cnt = sum_m hist[n][m]
//    v[i]  = B1[i,x[n],g] * tv[i] / max(cnt,1);  norm = sum_i v
//    ll1 = log(norm); post1[i] = v[i]/norm
//    R staged in smem padded to 516 floats/g-row (conflict-free: 516 % 32 = 4),
//    hist rows padded to 33 ints (conflict-free broadcast).
// ---------------------------------------------------------------------------
__global__ void k_layer1(const int* __restrict__ x, float* __restrict__ out)
{
    __shared__ float s_R[Gg * 516];      // 16.5 KB
    __shared__ int   s_hist[32 * 33];    // 4.2 KB
    __shared__ int   s_x[32];

    int t   = threadIdx.x;
    int bn0 = blockIdx.x * 32;

    // cooperative load of R: thread t -> 16 consecutive floats of g-row (t>>5)
    {
        int g   = t >> 5;
        int rem = (t & 31) * 16;
        const float4* src = reinterpret_cast<const float4*>(g_R + g * (Mm*Cc) + rem);
        float4*       dst = reinterpret_cast<float4*>(s_R + g * 516 + rem);
        dst[0] = src[0]; dst[1] = src[1]; dst[2] = src[2]; dst[3] = src[3];
    }
    // cooperative load of hist: thread t -> 4 ints of node-row (t>>3)
    {
        int nl  = t >> 3;
        int col = (t & 7) * 4;
        if (bn0 + nl < Nn) {
            int4 h4 = *reinterpret_cast<const int4*>(g_hist + (size_t)(bn0 + nl) * Mm + col);
            int* hp = s_hist + nl * 33 + col;
            hp[0] = h4.x; hp[1] = h4.y; hp[2] = h4.z; hp[3] = h4.w;
        }
    }
    if (t < 32 && bn0 + t < Nn) s_x[t] = x[bn0 + t];
    __syncthreads();

    int nl = t >> 3, g = t & 7;
    int n  = bn0 + nl;
    if (n >= Nn) return;
    int xm = s_x[nl];

    float tv[Cc];
    #pragma unroll
    for (int i = 0; i < Cc; i++) tv[i] = 0.f;
    float cnt = 0.f;

    const float* Rg = s_R + g * 516;
    const int*   hp = s_hist + nl * 33;

    #pragma unroll
    for (int m = 0; m < Mm; m++) {
        float h = (float)hp[m];
        cnt += h;
        const float4* r4 = reinterpret_cast<const float4*>(Rg + m * Cc);
        float4 r0 = r4[0], r1 = r4[1], r2 = r4[2], r3 = r4[3];
        tv[ 0] += h * r0.x; tv[ 1] += h * r0.y; tv[ 2] += h * r0.z; tv[ 3] += h * r0.w;
        tv[ 4] += h * r1.x; tv[ 5] += h * r1.y; tv[ 6] += h * r1.z; tv[ 7] += h * r1.w;
        tv[ 8] += h * r2.x; tv[ 9] += h * r2.y; tv[10] += h * r2.z; tv[11] += h * r2.w;
        tv[12] += h * r3.x; tv[13] += h * r3.y; tv[14] += h * r3.z; tv[15] += h * r3.w;
    }

    float inv_cnt = 1.f / fmaxf(cnt, 1.f);
    float norm = 0.f;
    #pragma unroll
    for (int i = 0; i < Cc; i++) {
        float v = g_smB1[i*Mm*Gg + xm*Gg + g] * tv[i] * inv_cnt;
        tv[i] = v;
        norm += v;
    }

    out[(size_t)n * (2*Gg) + g]      = g_ll0[xm*Gg + g];   // ll layer 0
    out[(size_t)n * (2*Gg) + Gg + g] = logf(norm);         // ll layer 1

    float invn = 1.f / norm;
    float* p1 = out + (size_t)Nn * 2 * Gg;
    size_t pbase = (size_t)n * CG + g;
    #pragma unroll
    for (int i = 0; i < Cc; i++) p1[pbase + i*Gg] = tv[i] * invn;
}

// ---------------------------------------------------------------------------
extern "C" void kernel_launch(void* const* d_in, const int* in_sizes, int n_in,
                              void* d_out, int out_size)
{
    const int*   x  = (const int*)  d_in[0];
    const int*   ei = (const int*)  d_in[1];   // [2, E]
    const float* B0 = (const float*)d_in[2];
    const float* Pi = (const float*)d_in[3];
    const float* B1 = (const float*)d_in[4];
    const float* Q  = (const float*)d_in[5];
    float* out = (float*)d_out;

    k_softmax<<<1, 256>>>(B0, Pi, B1, Q);
    k_zero_hist<<<(Nn * Mm / 4 + 255) / 256, 256>>>();
    k_scatter<<<(En / 4 + 255) / 256, 256>>>(ei, x);
    k_layer1<<<(Nn + 31) / 32, 256>>>(x, out);
}